// round 3
// baseline (speedup 1.0000x reference)
#include <cuda_runtime.h>

// ---------------------------------------------------------------------------
// DeformableConv2d: B=8, C=64, H=W=128, O=64, K=3, stride=1, pad=1, dil=1
// Inputs (metadata order): x(8,64,128,128) f32, weight(64,64,3,3) f32,
//                          bias(64) f32, off_w(18,64,3,3) f32, off_b(18) f32
// Output: (8,64,128,128) f32 NCHW
// ---------------------------------------------------------------------------

#define BB 8
#define CC 64
#define HH 128
#define WW 128
#define OO 64
#define KTAPS 9
#define CK 576  // 9*64

// Scratch (static device globals; no runtime allocation)
__device__ float g_x[(size_t)BB * HH * WW * CC];    // x in NHWC
__device__ float g_off[(size_t)BB * HH * WW * 18];  // offsets, NHWC-18
__device__ float g_wt[CK * OO];                     // weight re-laid as [k*64+c][o]

// ---- f32x2 packed math helpers (FFMA2 only reachable via PTX) --------------
__device__ __forceinline__ void ffma2(unsigned long long& d, unsigned long long a,
                                      unsigned long long b) {
    asm("fma.rn.f32x2 %0, %1, %2, %0;" : "+l"(d) : "l"(a), "l"(b));
}
__device__ __forceinline__ unsigned long long pack2(float x, float y) {
    unsigned long long r;
    asm("mov.b64 %0, {%1, %2};" : "=l"(r) : "f"(x), "f"(y));
    return r;
}
__device__ __forceinline__ float2 unpack2(unsigned long long v) {
    float2 r;
    asm("mov.b64 {%0, %1}, %2;" : "=f"(r.x), "=f"(r.y) : "l"(v));
    return r;
}

// ---------------------------------------------------------------------------
// Kernel 1: NCHW -> NHWC transpose of x (tiled through smem)
// grid (B*H, W/32, C/32), block (32, 8)
// ---------------------------------------------------------------------------
__global__ void k_transpose(const float* __restrict__ x) {
    __shared__ float tile[32][33];
    int bh = blockIdx.x;  // b*128 + h
    int w0 = blockIdx.y * 32;
    int c0 = blockIdx.z * 32;
    int b = bh >> 7;
    const float* src = x + ((size_t)(b * CC) * HH + (bh & 127)) * WW;
#pragma unroll
    for (int i = 0; i < 32; i += 8) {
        int c = c0 + threadIdx.y + i;
        tile[threadIdx.y + i][threadIdx.x] = src[(size_t)c * HH * WW + w0 + threadIdx.x];
    }
    __syncthreads();
    float* dst = g_x + (size_t)bh * WW * CC;
#pragma unroll
    for (int i = 0; i < 32; i += 8) {
        int w = w0 + threadIdx.y + i;
        dst[(size_t)w * CC + c0 + threadIdx.x] = tile[threadIdx.x][threadIdx.y + i];
    }
}

// ---------------------------------------------------------------------------
// Kernel 2: weight (O,C,3,3) -> g_wt[(k*64+c)*64 + o]
// ---------------------------------------------------------------------------
__global__ void k_wt(const float* __restrict__ w) {
    int idx = blockIdx.x * 256 + threadIdx.x;
    if (idx >= CK * OO) return;
    int ck = idx >> 6, o = idx & 63;
    int k = ck >> 6, c = ck & 63;
    g_wt[idx] = w[(o * CC + c) * KTAPS + k];
}

// ---------------------------------------------------------------------------
// Kernel 3: offset-predictor conv (18 out channels, 3x3, pad 1) on NHWC x.
// grid (W/16, H/16, B), block (16,16). Output g_off[b][i][j][18].
// Weights staged in smem as wo[tap][c][20] (oc padded 18->20 for float4/f32x2).
// ---------------------------------------------------------------------------
__global__ void k_off(const float* __restrict__ off_w, const float* __restrict__ off_b) {
    __shared__ float wo[9][64][20];  // 46080 B
    int tid = threadIdx.y * 16 + threadIdx.x;
    for (int idx = tid; idx < 9 * 64 * 20; idx += 256) {
        int tap = idx / 1280;
        int r = idx - tap * 1280;
        int c = r / 20;
        int oc = r - c * 20;
        wo[tap][c][oc] = (oc < 18) ? off_w[(oc * CC + c) * KTAPS + tap] : 0.f;
    }
    __syncthreads();

    int b = blockIdx.z;
    int i = blockIdx.y * 16 + threadIdx.y;
    int j = blockIdx.x * 16 + threadIdx.x;

    unsigned long long acc[10];
#pragma unroll
    for (int t = 0; t < 9; t++) acc[t] = pack2(__ldg(&off_b[2 * t]), __ldg(&off_b[2 * t + 1]));
    acc[9] = 0ull;

    const float* xb = g_x + (size_t)b * HH * WW * CC;
#pragma unroll
    for (int tap = 0; tap < 9; tap++) {
        int y = i + tap / 3 - 1;
        int x = j + (tap % 3) - 1;
        if ((unsigned)y >= HH || (unsigned)x >= WW) continue;  // zero padding
        const float4* xr = (const float4*)(xb + ((size_t)y * WW + x) * CC);
#pragma unroll 4
        for (int c4 = 0; c4 < 16; c4++) {
            float4 xv = xr[c4];
            float xs[4] = {xv.x, xv.y, xv.z, xv.w};
#pragma unroll
            for (int cc = 0; cc < 4; cc++) {
                unsigned long long xp = pack2(xs[cc], xs[cc]);
                const ulonglong2* wv = (const ulonglong2*)wo[tap][c4 * 4 + cc];
#pragma unroll
                for (int q = 0; q < 5; q++) {
                    ulonglong2 ww = wv[q];
                    ffma2(acc[2 * q], xp, ww.x);
                    ffma2(acc[2 * q + 1], xp, ww.y);
                }
            }
        }
    }
    float* outp = g_off + ((size_t)(b * HH + i) * WW + j) * 18;
#pragma unroll
    for (int t = 0; t < 9; t++) {
        float2 v = unpack2(acc[t]);
        outp[2 * t] = v.x;
        outp[2 * t + 1] = v.y;
    }
}

// ---------------------------------------------------------------------------
// Kernel 4: main deformable conv.
// grid (W/16, H, B), block 128. One block = 16-pixel output row segment.
// Phase 1: bilinear-gather sampled[p][k*64+c] into smem (16 threads per (p,k),
//          float4 over channels from NHWC x).
// Phase 2: out[p][o] = sum_ck samp[p][ck] * wt[ck][o]; 2 ck-halves per thread,
//          2-pixel x 8-output register tile, f32x2 FMAs, smem reduction.
// ---------------------------------------------------------------------------
#define SROW 580  // 576 padded; 580%32=4 breaks p/p+1 bank collision, 16B aligned

__global__ __launch_bounds__(128) void k_main(const float* __restrict__ bias,
                                              float* __restrict__ out) {
    __shared__ float samp[16 * SROW];  // 37120 B
    __shared__ float offs[16][18];

    int tid = threadIdx.x;
    int b = blockIdx.z, i = blockIdx.y, j0 = blockIdx.x * 16;

    // stage the 16 pixels' offsets
    for (int idx = tid; idx < 16 * 18; idx += 128) {
        int p = idx / 18, ch = idx - p * 18;
        offs[p][ch] = g_off[((size_t)(b * HH + i) * WW + j0 + p) * 18 + ch];
    }
    __syncthreads();

    // ---------------- Phase 1: gather ----------------
    {
        int g = tid >> 4, lane = tid & 15;
        const float* xb = g_x + (size_t)b * HH * WW * CC;
#pragma unroll 2
        for (int it = 0; it < 18; it++) {
            int pk = it * 8 + g;  // 0..143
            int p = pk / 9, k = pk - p * 9;
            float oy = offs[p][2 * k], ox = offs[p][2 * k + 1];
            // reference: sy = i + (k/3) + oy ; sx = j + (k%3) + ox
            float sy = (float)(i + k / 3) + oy;
            float sx = (float)(j0 + p + (k - (k / 3) * 3)) + ox;
            float fy = floorf(sy), fx = floorf(sx);
            float wy1 = sy - fy, wx1 = sx - fx;
            float wy0 = 1.f - wy1, wx0 = 1.f - wx1;
            int iy = (int)fy, ix = (int)fx;
            float tw[4] = {wy0 * wx0, wy0 * wx1, wy1 * wx0, wy1 * wx1};
            int ty[4] = {iy, iy, iy + 1, iy + 1};
            int tx[4] = {ix, ix + 1, ix, ix + 1};
            float4 acc = {0.f, 0.f, 0.f, 0.f};
#pragma unroll
            for (int tapi = 0; tapi < 4; tapi++) {
                int yy = ty[tapi], xx = tx[tapi];
                if ((unsigned)yy < HH && (unsigned)xx < WW) {
                    float4 xv =
                        *(const float4*)(xb + ((size_t)yy * WW + xx) * CC + lane * 4);
                    float w = tw[tapi];
                    acc.x += w * xv.x;
                    acc.y += w * xv.y;
                    acc.z += w * xv.z;
                    acc.w += w * xv.w;
                }
            }
            *(float4*)&samp[p * SROW + k * 64 + lane * 4] = acc;
        }
    }
    __syncthreads();

    // ---------------- Phase 2: contraction ----------------
    int ckh = tid >> 6;   // ck half: 0 -> [0,288), 1 -> [288,576)
    int t = tid & 63;
    int q = t >> 3;       // 0..7 -> pixel pair
    int p0 = q * 2;
    int og = t & 7;
    int o = og * 8;

    unsigned long long a0[4] = {0ull, 0ull, 0ull, 0ull};
    unsigned long long a1[4] = {0ull, 0ull, 0ull, 0ull};

    const float* s0p = &samp[p0 * SROW + ckh * 288];
    const float* s1p = &samp[(p0 + 1) * SROW + ckh * 288];
    const ulonglong2* wp = (const ulonglong2*)(g_wt + (size_t)(ckh * 288) * OO + o);

#pragma unroll 4
    for (int it = 0; it < 288; it++) {
        float s0 = s0p[it], s1 = s1p[it];
        unsigned long long s0b = pack2(s0, s0);
        unsigned long long s1b = pack2(s1, s1);
        ulonglong2 wa = wp[it * 16];       // w[o..o+3]
        ulonglong2 wb = wp[it * 16 + 1];   // w[o+4..o+7]
        ffma2(a0[0], s0b, wa.x);
        ffma2(a0[1], s0b, wa.y);
        ffma2(a0[2], s0b, wb.x);
        ffma2(a0[3], s0b, wb.y);
        ffma2(a1[0], s1b, wa.x);
        ffma2(a1[1], s1b, wa.y);
        ffma2(a1[2], s1b, wb.x);
        ffma2(a1[3], s1b, wb.y);
    }

    __syncthreads();  // samp fully consumed; reuse as reduction buffer
    float* red = samp;  // red[ckh][p][o] : 2*16*64 = 2048 floats
    {
        float* r0 = &red[(ckh * 16 + p0) * 64 + o];
        float* r1 = &red[(ckh * 16 + p0 + 1) * 64 + o];
#pragma unroll
        for (int u = 0; u < 4; u++) {
            float2 v0 = unpack2(a0[u]);
            float2 v1 = unpack2(a1[u]);
            r0[2 * u] = v0.x;
            r0[2 * u + 1] = v0.y;
            r1[2 * u] = v1.x;
            r1[2 * u + 1] = v1.y;
        }
    }
    __syncthreads();

    // final sum of halves + bias, coalesced NCHW store
    for (int idx = tid; idx < 1024; idx += 128) {
        int oo = idx >> 4, p = idx & 15;
        float v = red[p * 64 + oo] + red[(16 + p) * 64 + oo] + __ldg(&bias[oo]);
        out[((size_t)(b * OO + oo) * HH + i) * WW + j0 + p] = v;
    }
}

// ---------------------------------------------------------------------------
extern "C" void kernel_launch(void* const* d_in, const int* in_sizes, int n_in,
                              void* d_out, int out_size) {
    const float* x = (const float*)d_in[0];
    const float* weight = (const float*)d_in[1];
    const float* bias = (const float*)d_in[2];
    const float* off_w = (const float*)d_in[3];
    const float* off_b = (const float*)d_in[4];
    float* out = (float*)d_out;

    k_transpose<<<dim3(BB * HH, WW / 32, CC / 32), dim3(32, 8)>>>(x);
    k_wt<<<(CK * OO + 255) / 256, 256>>>(weight);
    k_off<<<dim3(WW / 16, HH / 16, BB), dim3(16, 16)>>>(off_w, off_b);
    k_main<<<dim3(WW / 16, HH, BB), 128>>>(bias, out);
}

// round 4
// speedup vs baseline: 1.0016x; 1.0016x over previous
#include <cuda_runtime.h>

// ---------------------------------------------------------------------------
// DeformableConv2d: B=8, C=64, H=W=128, O=64, K=3, stride=1, pad=1, dil=1
// Inputs (metadata order): x(8,64,128,128) f32, weight(64,64,3,3) f32,
//                          bias(64) f32, off_w(18,64,3,3) f32, off_b(18) f32
// Output: (8,64,128,128) f32 NCHW
// ---------------------------------------------------------------------------

#define BB 8
#define CC 64
#define HH 128
#define WW 128
#define OO 64
#define KTAPS 9
#define CK 576  // 9*64

// Scratch (static device globals; no runtime allocation)
__device__ float g_x[(size_t)BB * HH * WW * CC];    // x in NHWC
__device__ float g_off[(size_t)BB * HH * WW * 18];  // offsets, NHWC-18
__device__ float g_wt[CK * OO];                     // weight re-laid as [k*64+c][o]

// ---- f32x2 packed math helpers (FFMA2 only reachable via PTX) --------------
__device__ __forceinline__ void ffma2(unsigned long long& d, unsigned long long a,
                                      unsigned long long b) {
    asm("fma.rn.f32x2 %0, %1, %2, %0;" : "+l"(d) : "l"(a), "l"(b));
}
__device__ __forceinline__ unsigned long long pack2(float x, float y) {
    unsigned long long r;
    asm("mov.b64 %0, {%1, %2};" : "=l"(r) : "f"(x), "f"(y));
    return r;
}
__device__ __forceinline__ float2 unpack2(unsigned long long v) {
    float2 r;
    asm("mov.b64 {%0, %1}, %2;" : "=f"(r.x), "=f"(r.y) : "l"(v));
    return r;
}

// ---------------------------------------------------------------------------
// Kernel 1: NCHW -> NHWC transpose of x (tiled through smem)
// grid (B*H, W/32, C/32), block (32, 8)
// ---------------------------------------------------------------------------
__global__ void k_transpose(const float* __restrict__ x) {
    __shared__ float tile[32][33];
    int bh = blockIdx.x;  // b*128 + h
    int w0 = blockIdx.y * 32;
    int c0 = blockIdx.z * 32;
    int b = bh >> 7;
    const float* src = x + ((size_t)(b * CC) * HH + (bh & 127)) * WW;
#pragma unroll
    for (int i = 0; i < 32; i += 8) {
        int c = c0 + threadIdx.y + i;
        tile[threadIdx.y + i][threadIdx.x] = src[(size_t)c * HH * WW + w0 + threadIdx.x];
    }
    __syncthreads();
    float* dst = g_x + (size_t)bh * WW * CC;
#pragma unroll
    for (int i = 0; i < 32; i += 8) {
        int w = w0 + threadIdx.y + i;
        dst[(size_t)w * CC + c0 + threadIdx.x] = tile[threadIdx.x][threadIdx.y + i];
    }
}

// ---------------------------------------------------------------------------
// Kernel 2: weight (O,C,3,3) -> g_wt[(k*64+c)*64 + o]
// ---------------------------------------------------------------------------
__global__ void k_wt(const float* __restrict__ w) {
    int idx = blockIdx.x * 256 + threadIdx.x;
    if (idx >= CK * OO) return;
    int ck = idx >> 6, o = idx & 63;
    int k = ck >> 6, c = ck & 63;
    g_wt[idx] = w[(o * CC + c) * KTAPS + k];
}

// ---------------------------------------------------------------------------
// Kernel 3: offset-predictor conv (18 out channels, 3x3, pad 1) on NHWC x.
// grid (W/16, H/16, B), block (16,16). Output g_off[b][i][j][18].
// Weights staged in smem as wo[tap][c][20] (oc padded 18->20 for float4/f32x2).
// ---------------------------------------------------------------------------
__global__ void k_off(const float* __restrict__ off_w, const float* __restrict__ off_b) {
    __shared__ float wo[9][64][20];  // 46080 B
    int tid = threadIdx.y * 16 + threadIdx.x;
    for (int idx = tid; idx < 9 * 64 * 20; idx += 256) {
        int tap = idx / 1280;
        int r = idx - tap * 1280;
        int c = r / 20;
        int oc = r - c * 20;
        wo[tap][c][oc] = (oc < 18) ? off_w[(oc * CC + c) * KTAPS + tap] : 0.f;
    }
    __syncthreads();

    int b = blockIdx.z;
    int i = blockIdx.y * 16 + threadIdx.y;
    int j = blockIdx.x * 16 + threadIdx.x;

    unsigned long long acc[10];
#pragma unroll
    for (int t = 0; t < 9; t++) acc[t] = pack2(__ldg(&off_b[2 * t]), __ldg(&off_b[2 * t + 1]));
    acc[9] = 0ull;

    const float* xb = g_x + (size_t)b * HH * WW * CC;
#pragma unroll
    for (int tap = 0; tap < 9; tap++) {
        int y = i + tap / 3 - 1;
        int x = j + (tap % 3) - 1;
        if ((unsigned)y >= HH || (unsigned)x >= WW) continue;  // zero padding
        const float4* xr = (const float4*)(xb + ((size_t)y * WW + x) * CC);
#pragma unroll 4
        for (int c4 = 0; c4 < 16; c4++) {
            float4 xv = xr[c4];
            float xs[4] = {xv.x, xv.y, xv.z, xv.w};
#pragma unroll
            for (int cc = 0; cc < 4; cc++) {
                unsigned long long xp = pack2(xs[cc], xs[cc]);
                const ulonglong2* wv = (const ulonglong2*)wo[tap][c4 * 4 + cc];
#pragma unroll
                for (int q = 0; q < 5; q++) {
                    ulonglong2 ww = wv[q];
                    ffma2(acc[2 * q], xp, ww.x);
                    ffma2(acc[2 * q + 1], xp, ww.y);
                }
            }
        }
    }
    float* outp = g_off + ((size_t)(b * HH + i) * WW + j) * 18;
#pragma unroll
    for (int t = 0; t < 9; t++) {
        float2 v = unpack2(acc[t]);
        outp[2 * t] = v.x;
        outp[2 * t + 1] = v.y;
    }
}

// ---------------------------------------------------------------------------
// Kernel 4: main deformable conv.
// grid (W/16, H, B), block 128. One block = 16-pixel output row segment.
// Phase 1: bilinear-gather sampled[p][k*64+c] into smem (16 threads per (p,k),
//          float4 over channels from NHWC x).
// Phase 2: out[p][o] = sum_ck samp[p][ck] * wt[ck][o]; 2 ck-halves per thread,
//          2-pixel x 8-output register tile, f32x2 FMAs, smem reduction.
// ---------------------------------------------------------------------------
#define SROW 580  // 576 padded; 580%32=4 breaks p/p+1 bank collision, 16B aligned

__global__ __launch_bounds__(128) void k_main(const float* __restrict__ bias,
                                              float* __restrict__ out) {
    __shared__ float samp[16 * SROW];  // 37120 B
    __shared__ float offs[16][18];

    int tid = threadIdx.x;
    int b = blockIdx.z, i = blockIdx.y, j0 = blockIdx.x * 16;

    // stage the 16 pixels' offsets
    for (int idx = tid; idx < 16 * 18; idx += 128) {
        int p = idx / 18, ch = idx - p * 18;
        offs[p][ch] = g_off[((size_t)(b * HH + i) * WW + j0 + p) * 18 + ch];
    }
    __syncthreads();

    // ---------------- Phase 1: gather ----------------
    {
        int g = tid >> 4, lane = tid & 15;
        const float* xb = g_x + (size_t)b * HH * WW * CC;
#pragma unroll 2
        for (int it = 0; it < 18; it++) {
            int pk = it * 8 + g;  // 0..143
            int p = pk / 9, k = pk - p * 9;
            float oy = offs[p][2 * k], ox = offs[p][2 * k + 1];
            // reference: sy = i + (k/3) + oy ; sx = j + (k%3) + ox
            float sy = (float)(i + k / 3) + oy;
            float sx = (float)(j0 + p + (k - (k / 3) * 3)) + ox;
            float fy = floorf(sy), fx = floorf(sx);
            float wy1 = sy - fy, wx1 = sx - fx;
            float wy0 = 1.f - wy1, wx0 = 1.f - wx1;
            int iy = (int)fy, ix = (int)fx;
            float tw[4] = {wy0 * wx0, wy0 * wx1, wy1 * wx0, wy1 * wx1};
            int ty[4] = {iy, iy, iy + 1, iy + 1};
            int tx[4] = {ix, ix + 1, ix, ix + 1};
            float4 acc = {0.f, 0.f, 0.f, 0.f};
#pragma unroll
            for (int tapi = 0; tapi < 4; tapi++) {
                int yy = ty[tapi], xx = tx[tapi];
                if ((unsigned)yy < HH && (unsigned)xx < WW) {
                    float4 xv =
                        *(const float4*)(xb + ((size_t)yy * WW + xx) * CC + lane * 4);
                    float w = tw[tapi];
                    acc.x += w * xv.x;
                    acc.y += w * xv.y;
                    acc.z += w * xv.z;
                    acc.w += w * xv.w;
                }
            }
            *(float4*)&samp[p * SROW + k * 64 + lane * 4] = acc;
        }
    }
    __syncthreads();

    // ---------------- Phase 2: contraction ----------------
    int ckh = tid >> 6;   // ck half: 0 -> [0,288), 1 -> [288,576)
    int t = tid & 63;
    int q = t >> 3;       // 0..7 -> pixel pair
    int p0 = q * 2;
    int og = t & 7;
    int o = og * 8;

    unsigned long long a0[4] = {0ull, 0ull, 0ull, 0ull};
    unsigned long long a1[4] = {0ull, 0ull, 0ull, 0ull};

    const float* s0p = &samp[p0 * SROW + ckh * 288];
    const float* s1p = &samp[(p0 + 1) * SROW + ckh * 288];
    const ulonglong2* wp = (const ulonglong2*)(g_wt + (size_t)(ckh * 288) * OO + o);

#pragma unroll 4
    for (int it = 0; it < 288; it++) {
        float s0 = s0p[it], s1 = s1p[it];
        unsigned long long s0b = pack2(s0, s0);
        unsigned long long s1b = pack2(s1, s1);
        ulonglong2 wa = wp[it * 16];       // w[o..o+3]
        ulonglong2 wb = wp[it * 16 + 1];   // w[o+4..o+7]
        ffma2(a0[0], s0b, wa.x);
        ffma2(a0[1], s0b, wa.y);
        ffma2(a0[2], s0b, wb.x);
        ffma2(a0[3], s0b, wb.y);
        ffma2(a1[0], s1b, wa.x);
        ffma2(a1[1], s1b, wa.y);
        ffma2(a1[2], s1b, wb.x);
        ffma2(a1[3], s1b, wb.y);
    }

    __syncthreads();  // samp fully consumed; reuse as reduction buffer
    float* red = samp;  // red[ckh][p][o] : 2*16*64 = 2048 floats
    {
        float* r0 = &red[(ckh * 16 + p0) * 64 + o];
        float* r1 = &red[(ckh * 16 + p0 + 1) * 64 + o];
#pragma unroll
        for (int u = 0; u < 4; u++) {
            float2 v0 = unpack2(a0[u]);
            float2 v1 = unpack2(a1[u]);
            r0[2 * u] = v0.x;
            r0[2 * u + 1] = v0.y;
            r1[2 * u] = v1.x;
            r1[2 * u + 1] = v1.y;
        }
    }
    __syncthreads();

    // final sum of halves + bias, coalesced NCHW store
    for (int idx = tid; idx < 1024; idx += 128) {
        int oo = idx >> 4, p = idx & 15;
        float v = red[p * 64 + oo] + red[(16 + p) * 64 + oo] + __ldg(&bias[oo]);
        out[((size_t)(b * OO + oo) * HH + i) * WW + j0 + p] = v;
    }
}

// ---------------------------------------------------------------------------
extern "C" void kernel_launch(void* const* d_in, const int* in_sizes, int n_in,
                              void* d_out, int out_size) {
    const float* x = (const float*)d_in[0];
    const float* weight = (const float*)d_in[1];
    const float* bias = (const float*)d_in[2];
    const float* off_w = (const float*)d_in[3];
    const float* off_b = (const float*)d_in[4];
    float* out = (float*)d_out;

    k_transpose<<<dim3(BB * HH, WW / 32, CC / 32), dim3(32, 8)>>>(x);
    k_wt<<<(CK * OO + 255) / 256, 256>>>(weight);
    k_off<<<dim3(WW / 16, HH / 16, BB), dim3(16, 16)>>>(off_w, off_b);
    k_main<<<dim3(WW / 16, HH, BB), 128>>>(bias, out);
}

// round 5
// speedup vs baseline: 1.7339x; 1.7312x over previous
#include <cuda_runtime.h>

// ---------------------------------------------------------------------------
// DeformableConv2d: B=8, C=64, H=W=128, O=64, K=3, stride=1, pad=1, dil=1
// Inputs (metadata order): x(8,64,128,128) f32, weight(64,64,3,3) f32,
//                          bias(64) f32, off_w(18,64,3,3) f32, off_b(18) f32
// Output: (8,64,128,128) f32 NCHW
// ---------------------------------------------------------------------------

#define BB 8
#define CC 64
#define HH 128
#define WW 128
#define OO 64
#define KTAPS 9
#define CK 576  // 9*64

// Scratch (static device globals; no runtime allocation)
__device__ float g_x[(size_t)BB * HH * WW * CC];    // x in NHWC
__device__ float g_off[(size_t)BB * HH * WW * 18];  // offsets, NHWC-18
__device__ float g_wt[CK * OO];                     // weight re-laid as [k*64+c][o]

// ---- f32x2 packed math helpers (FFMA2 only reachable via PTX) --------------
__device__ __forceinline__ void ffma2(unsigned long long& d, unsigned long long a,
                                      unsigned long long b) {
    asm("fma.rn.f32x2 %0, %1, %2, %0;" : "+l"(d) : "l"(a), "l"(b));
}
__device__ __forceinline__ unsigned long long pack2(float x, float y) {
    unsigned long long r;
    asm("mov.b64 %0, {%1, %2};" : "=l"(r) : "f"(x), "f"(y));
    return r;
}
__device__ __forceinline__ float2 unpack2(unsigned long long v) {
    float2 r;
    asm("mov.b64 {%0, %1}, %2;" : "=f"(r.x), "=f"(r.y) : "l"(v));
    return r;
}

// ---------------------------------------------------------------------------
// Kernel 1: NCHW -> NHWC transpose of x (tiled through smem)
// grid (B*H, W/32, C/32), block (32, 8)
// ---------------------------------------------------------------------------
__global__ void k_transpose(const float* __restrict__ x) {
    __shared__ float tile[32][33];
    int bh = blockIdx.x;  // b*128 + h
    int w0 = blockIdx.y * 32;
    int c0 = blockIdx.z * 32;
    int b = bh >> 7;
    const float* src = x + ((size_t)(b * CC) * HH + (bh & 127)) * WW;
#pragma unroll
    for (int i = 0; i < 32; i += 8) {
        int c = c0 + threadIdx.y + i;
        tile[threadIdx.y + i][threadIdx.x] = src[(size_t)c * HH * WW + w0 + threadIdx.x];
    }
    __syncthreads();
    float* dst = g_x + (size_t)bh * WW * CC;
#pragma unroll
    for (int i = 0; i < 32; i += 8) {
        int w = w0 + threadIdx.y + i;
        dst[(size_t)w * CC + c0 + threadIdx.x] = tile[threadIdx.x][threadIdx.y + i];
    }
}

// ---------------------------------------------------------------------------
// Kernel 2: weight (O,C,3,3) -> g_wt[(k*64+c)*64 + o]
// ---------------------------------------------------------------------------
__global__ void k_wt(const float* __restrict__ w) {
    int idx = blockIdx.x * 256 + threadIdx.x;
    if (idx >= CK * OO) return;
    int ck = idx >> 6, o = idx & 63;
    int k = ck >> 6, c = ck & 63;
    g_wt[idx] = w[(o * CC + c) * KTAPS + k];
}

// ---------------------------------------------------------------------------
// Kernel 3: offset-predictor conv (18 out channels, 3x3, pad 1) on NHWC x.
// grid (W/16, H/16, B), block (16,16). Output g_off[b][i][j][18].
// ---------------------------------------------------------------------------
__global__ void k_off(const float* __restrict__ off_w, const float* __restrict__ off_b) {
    __shared__ float wo[9][64][20];  // 46080 B
    int tid = threadIdx.y * 16 + threadIdx.x;
    for (int idx = tid; idx < 9 * 64 * 20; idx += 256) {
        int tap = idx / 1280;
        int r = idx - tap * 1280;
        int c = r / 20;
        int oc = r - c * 20;
        wo[tap][c][oc] = (oc < 18) ? off_w[(oc * CC + c) * KTAPS + tap] : 0.f;
    }
    __syncthreads();

    int b = blockIdx.z;
    int i = blockIdx.y * 16 + threadIdx.y;
    int j = blockIdx.x * 16 + threadIdx.x;

    unsigned long long acc[10];
#pragma unroll
    for (int t = 0; t < 9; t++) acc[t] = pack2(__ldg(&off_b[2 * t]), __ldg(&off_b[2 * t + 1]));
    acc[9] = 0ull;

    const float* xb = g_x + (size_t)b * HH * WW * CC;
#pragma unroll
    for (int tap = 0; tap < 9; tap++) {
        int y = i + tap / 3 - 1;
        int x = j + (tap % 3) - 1;
        if ((unsigned)y >= HH || (unsigned)x >= WW) continue;  // zero padding
        const float4* xr = (const float4*)(xb + ((size_t)y * WW + x) * CC);
#pragma unroll 4
        for (int c4 = 0; c4 < 16; c4++) {
            float4 xv = xr[c4];
            float xs[4] = {xv.x, xv.y, xv.z, xv.w};
#pragma unroll
            for (int cc = 0; cc < 4; cc++) {
                unsigned long long xp = pack2(xs[cc], xs[cc]);
                const ulonglong2* wv = (const ulonglong2*)wo[tap][c4 * 4 + cc];
#pragma unroll
                for (int q = 0; q < 5; q++) {
                    ulonglong2 ww = wv[q];
                    ffma2(acc[2 * q], xp, ww.x);
                    ffma2(acc[2 * q + 1], xp, ww.y);
                }
            }
        }
    }
    float* outp = g_off + ((size_t)(b * HH + i) * WW + j) * 18;
#pragma unroll
    for (int t = 0; t < 9; t++) {
        float2 v = unpack2(acc[t]);
        outp[2 * t] = v.x;
        outp[2 * t + 1] = v.y;
    }
}

// ---------------------------------------------------------------------------
// Kernel 4: main deformable conv.
// grid (W/16, H, B), block 128. One block = 16-pixel output row segment.
// Phase 1: bilinear-gather sampled[p][k*64+c] into smem (16 threads per (p,k),
//          float4 over channels from NHWC x).
// Phase 2: out[p][o] = sum_ck samp[p][ck] * wt[ck][o].
//          4 K-chunks of 144 (one per warp); thread tile = 4 consecutive
//          pixels x 8 outputs, with outputs split {og*4..+3} U {32+og*4..+3}
//          so each weight LDG.128 is a dense 128B warp-wavefront.
//          f32x2 FMAs; 4-way partial reduction through reused smem.
// ---------------------------------------------------------------------------
#define SROW 580  // 576 padded; breaks p/p+1 bank collision, 16B aligned

__global__ __launch_bounds__(128) void k_main(const float* __restrict__ bias,
                                              float* __restrict__ out) {
    __shared__ float samp[16 * SROW];  // 37120 B
    __shared__ float offs[16][18];

    int tid = threadIdx.x;
    int b = blockIdx.z, i = blockIdx.y, j0 = blockIdx.x * 16;

    // stage the 16 pixels' offsets
    for (int idx = tid; idx < 16 * 18; idx += 128) {
        int p = idx / 18, ch = idx - p * 18;
        offs[p][ch] = g_off[((size_t)(b * HH + i) * WW + j0 + p) * 18 + ch];
    }
    __syncthreads();

    // ---------------- Phase 1: gather ----------------
    {
        int g = tid >> 4, lane = tid & 15;
        const float* xb = g_x + (size_t)b * HH * WW * CC;
#pragma unroll 2
        for (int it = 0; it < 18; it++) {
            int pk = it * 8 + g;  // 0..143
            int p = pk / 9, k = pk - p * 9;
            float oy = offs[p][2 * k], ox = offs[p][2 * k + 1];
            float sy = (float)(i + k / 3) + oy;
            float sx = (float)(j0 + p + (k - (k / 3) * 3)) + ox;
            float fy = floorf(sy), fx = floorf(sx);
            float wy1 = sy - fy, wx1 = sx - fx;
            float wy0 = 1.f - wy1, wx0 = 1.f - wx1;
            int iy = (int)fy, ix = (int)fx;
            float tw[4] = {wy0 * wx0, wy0 * wx1, wy1 * wx0, wy1 * wx1};
            int ty[4] = {iy, iy, iy + 1, iy + 1};
            int tx[4] = {ix, ix + 1, ix, ix + 1};
            float4 acc = {0.f, 0.f, 0.f, 0.f};
#pragma unroll
            for (int tapi = 0; tapi < 4; tapi++) {
                int yy = ty[tapi], xx = tx[tapi];
                if ((unsigned)yy < HH && (unsigned)xx < WW) {
                    float4 xv =
                        *(const float4*)(xb + ((size_t)yy * WW + xx) * CC + lane * 4);
                    float w = tw[tapi];
                    acc.x += w * xv.x;
                    acc.y += w * xv.y;
                    acc.z += w * xv.z;
                    acc.w += w * xv.w;
                }
            }
            *(float4*)&samp[p * SROW + k * 64 + lane * 4] = acc;
        }
    }
    __syncthreads();

    // ---------------- Phase 2: contraction ----------------
    int warp = tid >> 5;        // K chunk: ck in [warp*144, warp*144+144)
    int lane = tid & 31;
    int pg = lane >> 3;         // pixel group: pixels pg*4 .. pg*4+3
    int og = lane & 7;          // output group: {og*4..+3} and {32+og*4..+3}
    int p0 = pg * 4;
    int ck0 = warp * 144;

    unsigned long long a0[4] = {0, 0, 0, 0};
    unsigned long long a1[4] = {0, 0, 0, 0};
    unsigned long long a2[4] = {0, 0, 0, 0};
    unsigned long long a3[4] = {0, 0, 0, 0};

    const float* s0p = &samp[(p0 + 0) * SROW + ck0];
    const float* s1p = &samp[(p0 + 1) * SROW + ck0];
    const float* s2p = &samp[(p0 + 2) * SROW + ck0];
    const float* s3p = &samp[(p0 + 3) * SROW + ck0];
    const ulonglong2* wpa = (const ulonglong2*)(g_wt + (size_t)ck0 * OO + og * 4);
    const ulonglong2* wpb = (const ulonglong2*)(g_wt + (size_t)ck0 * OO + 32 + og * 4);

#pragma unroll 4
    for (int it = 0; it < 144; it++) {
        float v0 = s0p[it], v1 = s1p[it], v2 = s2p[it], v3 = s3p[it];
        unsigned long long sb0 = pack2(v0, v0);
        unsigned long long sb1 = pack2(v1, v1);
        unsigned long long sb2 = pack2(v2, v2);
        unsigned long long sb3 = pack2(v3, v3);
        ulonglong2 wa = wpa[it * 16];  // w[ck][og*4 .. og*4+3]      (dense 128B/warp)
        ulonglong2 wb = wpb[it * 16];  // w[ck][32+og*4 .. 32+og*4+3](dense 128B/warp)
        ffma2(a0[0], sb0, wa.x);
        ffma2(a0[1], sb0, wa.y);
        ffma2(a0[2], sb0, wb.x);
        ffma2(a0[3], sb0, wb.y);
        ffma2(a1[0], sb1, wa.x);
        ffma2(a1[1], sb1, wa.y);
        ffma2(a1[2], sb1, wb.x);
        ffma2(a1[3], sb1, wb.y);
        ffma2(a2[0], sb2, wa.x);
        ffma2(a2[1], sb2, wa.y);
        ffma2(a2[2], sb2, wb.x);
        ffma2(a2[3], sb2, wb.y);
        ffma2(a3[0], sb3, wa.x);
        ffma2(a3[1], sb3, wa.y);
        ffma2(a3[2], sb3, wb.x);
        ffma2(a3[3], sb3, wb.y);
    }

    __syncthreads();  // samp fully consumed; reuse as reduction buffer
    float* red = samp;  // red[warp][p][o] : 4*16*64 = 4096 floats
    {
        unsigned long long* accs[4] = {a0, a1, a2, a3};
#pragma unroll
        for (int u = 0; u < 4; u++) {
            float* r = &red[(warp * 16 + p0 + u) * 64];
            float2 q0 = unpack2(accs[u][0]);
            float2 q1 = unpack2(accs[u][1]);
            float2 q2 = unpack2(accs[u][2]);
            float2 q3 = unpack2(accs[u][3]);
            r[og * 4 + 0] = q0.x;
            r[og * 4 + 1] = q0.y;
            r[og * 4 + 2] = q1.x;
            r[og * 4 + 3] = q1.y;
            r[32 + og * 4 + 0] = q2.x;
            r[32 + og * 4 + 1] = q2.y;
            r[32 + og * 4 + 2] = q3.x;
            r[32 + og * 4 + 3] = q3.y;
        }
    }
    __syncthreads();

    // final sum of the 4 K-chunk partials + bias, coalesced NCHW store
    for (int idx = tid; idx < 1024; idx += 128) {
        int oo = idx >> 4, p = idx & 15;
        float v = red[p * 64 + oo] + red[(16 + p) * 64 + oo] +
                  red[(32 + p) * 64 + oo] + red[(48 + p) * 64 + oo] + __ldg(&bias[oo]);
        out[((size_t)(b * OO + oo) * HH + i) * WW + j0 + p] = v;
    }
}

// ---------------------------------------------------------------------------
extern "C" void kernel_launch(void* const* d_in, const int* in_sizes, int n_in,
                              void* d_out, int out_size) {
    const float* x = (const float*)d_in[0];
    const float* weight = (const float*)d_in[1];
    const float* bias = (const float*)d_in[2];
    const float* off_w = (const float*)d_in[3];
    const float* off_b = (const float*)d_in[4];
    float* out = (float*)d_out;

    k_transpose<<<dim3(BB * HH, WW / 32, CC / 32), dim3(32, 8)>>>(x);
    k_wt<<<(CK * OO + 255) / 256, 256>>>(weight);
    k_off<<<dim3(WW / 16, HH / 16, BB), dim3(16, 16)>>>(off_w, off_b);
    k_main<<<dim3(WW / 16, HH, BB), 128>>>(bias, out);
}

// round 6
// speedup vs baseline: 1.8351x; 1.0584x over previous
#include <cuda_runtime.h>

// ---------------------------------------------------------------------------
// DeformableConv2d: B=8, C=64, H=W=128, O=64, K=3, stride=1, pad=1, dil=1
// Inputs (metadata order): x(8,64,128,128) f32, weight(64,64,3,3) f32,
//                          bias(64) f32, off_w(18,64,3,3) f32, off_b(18) f32
// Output: (8,64,128,128) f32 NCHW
// ---------------------------------------------------------------------------

#define BB 8
#define CC 64
#define HH 128
#define WW 128
#define OO 64
#define KTAPS 9
#define CK 576  // 9*64

// Scratch (static device globals; no runtime allocation)
__device__ float g_x[(size_t)BB * HH * WW * CC];    // x in NHWC
__device__ float g_off[(size_t)BB * HH * WW * 18];  // offsets, NHWC-18
__device__ float g_wt[CK * OO];                     // weight re-laid as [k*64+c][o]

// ---- f32x2 packed math helpers (FFMA2 only reachable via PTX) --------------
__device__ __forceinline__ void ffma2(unsigned long long& d, unsigned long long a,
                                      unsigned long long b) {
    asm("fma.rn.f32x2 %0, %1, %2, %0;" : "+l"(d) : "l"(a), "l"(b));
}
__device__ __forceinline__ unsigned long long pack2(float x, float y) {
    unsigned long long r;
    asm("mov.b64 %0, {%1, %2};" : "=l"(r) : "f"(x), "f"(y));
    return r;
}
__device__ __forceinline__ float2 unpack2(unsigned long long v) {
    float2 r;
    asm("mov.b64 {%0, %1}, %2;" : "=f"(r.x), "=f"(r.y) : "l"(v));
    return r;
}

// ---------------------------------------------------------------------------
// Kernel 1: NCHW -> NHWC transpose of x (tiled through smem)
// grid (B*H, W/32, C/32), block (32, 8)
// ---------------------------------------------------------------------------
__global__ void k_transpose(const float* __restrict__ x) {
    __shared__ float tile[32][33];
    int bh = blockIdx.x;  // b*128 + h
    int w0 = blockIdx.y * 32;
    int c0 = blockIdx.z * 32;
    int b = bh >> 7;
    const float* src = x + ((size_t)(b * CC) * HH + (bh & 127)) * WW;
#pragma unroll
    for (int i = 0; i < 32; i += 8) {
        int c = c0 + threadIdx.y + i;
        tile[threadIdx.y + i][threadIdx.x] = src[(size_t)c * HH * WW + w0 + threadIdx.x];
    }
    __syncthreads();
    float* dst = g_x + (size_t)bh * WW * CC;
#pragma unroll
    for (int i = 0; i < 32; i += 8) {
        int w = w0 + threadIdx.y + i;
        dst[(size_t)w * CC + c0 + threadIdx.x] = tile[threadIdx.x][threadIdx.y + i];
    }
}

// ---------------------------------------------------------------------------
// Kernel 2: weight (O,C,3,3) -> g_wt[(k*64+c)*64 + o]
// ---------------------------------------------------------------------------
__global__ void k_wt(const float* __restrict__ w) {
    int idx = blockIdx.x * 256 + threadIdx.x;
    if (idx >= CK * OO) return;
    int ck = idx >> 6, o = idx & 63;
    int k = ck >> 6, c = ck & 63;
    g_wt[idx] = w[(o * CC + c) * KTAPS + k];
}

// ---------------------------------------------------------------------------
// Kernel 3: offset-predictor conv (18 out, 3x3, pad 1) on NHWC x.
// grid (W/16, H/16, B), block 256, one thread per output pixel.
// x tile (18x18 sites x 64 ch, channel stride padded to 66) + weights
// (9x64x20) both staged in DYNAMIC smem; all inner loads are LDS.
// Weight reads are warp-uniform broadcasts; x reads are <=2-way conflicted.
// ---------------------------------------------------------------------------
#define WO_FL (9 * 64 * 20)       // 11520 floats
#define XT_PAD 66
#define XT_FL (18 * 18 * XT_PAD)  // 21384 floats
#define KOFF_SMEM ((WO_FL + XT_FL) * 4)  // 131616 bytes

__global__ __launch_bounds__(256) void k_off(const float* __restrict__ off_w,
                                             const float* __restrict__ off_b) {
    extern __shared__ float sh[];
    float* wo = sh;            // [tap][c][20]
    float* xt = sh + WO_FL;    // [site(18*18)][66]

    int tid = threadIdx.x;
    int b = blockIdx.z;
    int i0 = blockIdx.y * 16, j0 = blockIdx.x * 16;

    // stage weights (oc padded 18->20)
    for (int idx = tid; idx < WO_FL; idx += 256) {
        int tap = idx / 1280;
        int r = idx - tap * 1280;
        int c = r / 20;
        int oc = r - c * 20;
        wo[idx] = (oc < 18) ? off_w[(oc * CC + c) * KTAPS + tap] : 0.f;
    }
    // stage x tile: sites (i0-1..i0+16, j0-1..j0+16), coalesced over channels
    const float* xb = g_x + (size_t)b * HH * WW * CC;
    for (int idx = tid; idx < 18 * 18 * 64; idx += 256) {
        int site = idx >> 6, c = idx & 63;
        int ry = site / 18, rx = site - ry * 18;
        int y = i0 + ry - 1, x = j0 + rx - 1;
        float v = 0.f;
        if ((unsigned)y < HH && (unsigned)x < WW) v = xb[((size_t)y * WW + x) * CC + c];
        xt[site * XT_PAD + c] = v;
    }
    __syncthreads();

    int r = tid >> 4, q = tid & 15;  // output pixel (i0+r, j0+q)

    unsigned long long acc[10];
#pragma unroll
    for (int t = 0; t < 9; t++) acc[t] = pack2(__ldg(&off_b[2 * t]), __ldg(&off_b[2 * t + 1]));
    acc[9] = 0ull;

#pragma unroll
    for (int tap = 0; tap < 9; tap++) {
        const float* xr = &xt[((r + tap / 3) * 18 + (q + tap % 3)) * XT_PAD];
        const float* wt = &wo[tap * 1280];
#pragma unroll 4
        for (int c2 = 0; c2 < 32; c2++) {
            float2 xv = *(const float2*)&xr[c2 * 2];
            unsigned long long xp0 = pack2(xv.x, xv.x);
            unsigned long long xp1 = pack2(xv.y, xv.y);
            const ulonglong2* wv0 = (const ulonglong2*)&wt[(c2 * 2) * 20];
            const ulonglong2* wv1 = (const ulonglong2*)&wt[(c2 * 2 + 1) * 20];
#pragma unroll
            for (int u = 0; u < 5; u++) {
                ulonglong2 w0 = wv0[u];
                ffma2(acc[2 * u], xp0, w0.x);
                ffma2(acc[2 * u + 1], xp0, w0.y);
            }
#pragma unroll
            for (int u = 0; u < 5; u++) {
                ulonglong2 w1 = wv1[u];
                ffma2(acc[2 * u], xp1, w1.x);
                ffma2(acc[2 * u + 1], xp1, w1.y);
            }
        }
    }
    float* outp = g_off + ((size_t)(b * HH + i0 + r) * WW + j0 + q) * 18;
#pragma unroll
    for (int t = 0; t < 9; t++) {
        float2 v = unpack2(acc[t]);
        outp[2 * t] = v.x;
        outp[2 * t + 1] = v.y;
    }
}

// ---------------------------------------------------------------------------
// Kernel 4: main deformable conv.
// grid (W/16, H, B), block 128. One block = 16-pixel output row segment.
// Phase 1: bilinear-gather sampled[p][k*64+c] into smem.
// Phase 2: out[p][o] = sum_ck samp[p][ck] * wt[ck][o].
//          4 K-chunks of 144 (one per warp); thread tile = 4 consecutive
//          pixels x 8 outputs ({og*4..+3} U {32+og*4..+3} -> dense 128B weight
//          LDG.128); samp read as float4 (4 ck per step, LDS.128).
// ---------------------------------------------------------------------------
#define SROW 580  // 576 padded; 16B aligned row stride

__global__ __launch_bounds__(128) void k_main(const float* __restrict__ bias,
                                              float* __restrict__ out) {
    __shared__ float samp[16 * SROW];  // 37120 B
    __shared__ float offs[16][18];

    int tid = threadIdx.x;
    int b = blockIdx.z, i = blockIdx.y, j0 = blockIdx.x * 16;

    for (int idx = tid; idx < 16 * 18; idx += 128) {
        int p = idx / 18, ch = idx - p * 18;
        offs[p][ch] = g_off[((size_t)(b * HH + i) * WW + j0 + p) * 18 + ch];
    }
    __syncthreads();

    // ---------------- Phase 1: gather ----------------
    {
        int g = tid >> 4, lane = tid & 15;
        const float* xb = g_x + (size_t)b * HH * WW * CC;
#pragma unroll 2
        for (int it = 0; it < 18; it++) {
            int pk = it * 8 + g;  // 0..143
            int p = pk / 9, k = pk - p * 9;
            float oy = offs[p][2 * k], ox = offs[p][2 * k + 1];
            float sy = (float)(i + k / 3) + oy;
            float sx = (float)(j0 + p + (k - (k / 3) * 3)) + ox;
            float fy = floorf(sy), fx = floorf(sx);
            float wy1 = sy - fy, wx1 = sx - fx;
            float wy0 = 1.f - wy1, wx0 = 1.f - wx1;
            int iy = (int)fy, ix = (int)fx;
            float tw[4] = {wy0 * wx0, wy0 * wx1, wy1 * wx0, wy1 * wx1};
            int ty[4] = {iy, iy, iy + 1, iy + 1};
            int tx[4] = {ix, ix + 1, ix, ix + 1};
            float4 acc = {0.f, 0.f, 0.f, 0.f};
#pragma unroll
            for (int tapi = 0; tapi < 4; tapi++) {
                int yy = ty[tapi], xx = tx[tapi];
                if ((unsigned)yy < HH && (unsigned)xx < WW) {
                    float4 xv =
                        *(const float4*)(xb + ((size_t)yy * WW + xx) * CC + lane * 4);
                    float w = tw[tapi];
                    acc.x += w * xv.x;
                    acc.y += w * xv.y;
                    acc.z += w * xv.z;
                    acc.w += w * xv.w;
                }
            }
            *(float4*)&samp[p * SROW + k * 64 + lane * 4] = acc;
        }
    }
    __syncthreads();

    // ---------------- Phase 2: contraction ----------------
    int warp = tid >> 5;        // K chunk: ck in [warp*144, warp*144+144)
    int lane = tid & 31;
    int pg = lane >> 3;         // pixel group: pixels pg*4 .. pg*4+3
    int og = lane & 7;          // output group: {og*4..+3} and {32+og*4..+3}
    int p0 = pg * 4;
    int ck0 = warp * 144;

    unsigned long long a0[4] = {0, 0, 0, 0};
    unsigned long long a1[4] = {0, 0, 0, 0};
    unsigned long long a2[4] = {0, 0, 0, 0};
    unsigned long long a3[4] = {0, 0, 0, 0};

    const float4* s0p = (const float4*)&samp[(p0 + 0) * SROW + ck0];
    const float4* s1p = (const float4*)&samp[(p0 + 1) * SROW + ck0];
    const float4* s2p = (const float4*)&samp[(p0 + 2) * SROW + ck0];
    const float4* s3p = (const float4*)&samp[(p0 + 3) * SROW + ck0];
    const ulonglong2* wpa = (const ulonglong2*)(g_wt + (size_t)ck0 * OO + og * 4);
    const ulonglong2* wpb = (const ulonglong2*)(g_wt + (size_t)ck0 * OO + 32 + og * 4);

#pragma unroll 2
    for (int it4 = 0; it4 < 36; it4++) {
        float v0[4], v1[4], v2[4], v3[4];
        *(float4*)v0 = s0p[it4];
        *(float4*)v1 = s1p[it4];
        *(float4*)v2 = s2p[it4];
        *(float4*)v3 = s3p[it4];
#pragma unroll
        for (int sub = 0; sub < 4; sub++) {
            int it = it4 * 4 + sub;
            unsigned long long sb0 = pack2(v0[sub], v0[sub]);
            unsigned long long sb1 = pack2(v1[sub], v1[sub]);
            unsigned long long sb2 = pack2(v2[sub], v2[sub]);
            unsigned long long sb3 = pack2(v3[sub], v3[sub]);
            ulonglong2 wa = wpa[it * 16];  // w[ck][og*4 .. +3]       dense 128B/warp
            ulonglong2 wb = wpb[it * 16];  // w[ck][32+og*4 .. +3]    dense 128B/warp
            ffma2(a0[0], sb0, wa.x);
            ffma2(a0[1], sb0, wa.y);
            ffma2(a0[2], sb0, wb.x);
            ffma2(a0[3], sb0, wb.y);
            ffma2(a1[0], sb1, wa.x);
            ffma2(a1[1], sb1, wa.y);
            ffma2(a1[2], sb1, wb.x);
            ffma2(a1[3], sb1, wb.y);
            ffma2(a2[0], sb2, wa.x);
            ffma2(a2[1], sb2, wa.y);
            ffma2(a2[2], sb2, wb.x);
            ffma2(a2[3], sb2, wb.y);
            ffma2(a3[0], sb3, wa.x);
            ffma2(a3[1], sb3, wa.y);
            ffma2(a3[2], sb3, wb.x);
            ffma2(a3[3], sb3, wb.y);
        }
    }

    __syncthreads();  // samp fully consumed; reuse as reduction buffer
    float* red = samp;  // red[warp][p][o] : 4*16*64 = 4096 floats
    {
        unsigned long long* accs[4] = {a0, a1, a2, a3};
#pragma unroll
        for (int u = 0; u < 4; u++) {
            float* r = &red[(warp * 16 + p0 + u) * 64];
            float2 q0 = unpack2(accs[u][0]);
            float2 q1 = unpack2(accs[u][1]);
            float2 q2 = unpack2(accs[u][2]);
            float2 q3 = unpack2(accs[u][3]);
            r[og * 4 + 0] = q0.x;
            r[og * 4 + 1] = q0.y;
            r[og * 4 + 2] = q1.x;
            r[og * 4 + 3] = q1.y;
            r[32 + og * 4 + 0] = q2.x;
            r[32 + og * 4 + 1] = q2.y;
            r[32 + og * 4 + 2] = q3.x;
            r[32 + og * 4 + 3] = q3.y;
        }
    }
    __syncthreads();

    // final sum of the 4 K-chunk partials + bias, coalesced NCHW store
    for (int idx = tid; idx < 1024; idx += 128) {
        int oo = idx >> 4, p = idx & 15;
        float v = red[p * 64 + oo] + red[(16 + p) * 64 + oo] +
                  red[(32 + p) * 64 + oo] + red[(48 + p) * 64 + oo] + __ldg(&bias[oo]);
        out[((size_t)(b * OO + oo) * HH + i) * WW + j0 + p] = v;
    }
}

// ---------------------------------------------------------------------------
extern "C" void kernel_launch(void* const* d_in, const int* in_sizes, int n_in,
                              void* d_out, int out_size) {
    const float* x = (const float*)d_in[0];
    const float* weight = (const float*)d_in[1];
    const float* bias = (const float*)d_in[2];
    const float* off_w = (const float*)d_in[3];
    const float* off_b = (const float*)d_in[4];
    float* out = (float*)d_out;

    // idempotent; not a stream op, safe under graph capture
    cudaFuncSetAttribute(k_off, cudaFuncAttributeMaxDynamicSharedMemorySize, KOFF_SMEM);

    k_transpose<<<dim3(BB * HH, WW / 32, CC / 32), dim3(32, 8)>>>(x);
    k_wt<<<(CK * OO + 255) / 256, 256>>>(weight);
    k_off<<<dim3(WW / 16, HH / 16, BB), 256, KOFF_SMEM>>>(off_w, off_b);
    k_main<<<dim3(WW / 16, HH, BB), 128>>>(bias, out);
}

// round 8
// speedup vs baseline: 2.4161x; 1.3166x over previous
#include <cuda_runtime.h>
#include <cuda_bf16.h>
#include <cstdint>

// ---------------------------------------------------------------------------
// DeformableConv2d: B=8, C=64, H=W=128, O=64, K=3, stride=1, pad=1, dil=1
// Main contraction on tensor cores via warp-level mma.sync (bf16 2-way split,
// fp32 accum) — plain sm_80+ PTX, assembles under .target sm_100.
// ---------------------------------------------------------------------------

#define BB 8
#define CC 64
#define HH 128
#define WW 128
#define OO 64
#define KPAD 584  // 576 + 8 pad (ushort); row stride 1168B, 16B-aligned

// Scratch (static device globals; no runtime allocation)
__device__ float g_x[(size_t)BB * HH * WW * CC];    // x in NHWC
__device__ float g_off[(size_t)BB * HH * WW * 18];  // offsets, NHWC-18
// B fragments for mma.sync m16n8k16: [k16(36)][n8(8)][split(2)][lane(32)][reg(2)]
__device__ uint32_t g_wfrag[36 * 8 * 2 * 32 * 2];

// ---- f32x2 packed math helpers (for k_off) ---------------------------------
__device__ __forceinline__ void ffma2(unsigned long long& d, unsigned long long a,
                                      unsigned long long b) {
    asm("fma.rn.f32x2 %0, %1, %2, %0;" : "+l"(d) : "l"(a), "l"(b));
}
__device__ __forceinline__ unsigned long long pack2(float x, float y) {
    unsigned long long r;
    asm("mov.b64 %0, {%1, %2};" : "=l"(r) : "f"(x), "f"(y));
    return r;
}
__device__ __forceinline__ float2 unpack2(unsigned long long v) {
    float2 r;
    asm("mov.b64 {%0, %1}, %2;" : "=f"(r.x), "=f"(r.y) : "l"(v));
    return r;
}

// ---- tensor-core helpers ---------------------------------------------------
__device__ __forceinline__ void ldmat4(uint32_t* a, uint32_t addr) {
    asm volatile("ldmatrix.sync.aligned.m8n8.x4.shared.b16 {%0,%1,%2,%3}, [%4];"
                 : "=r"(a[0]), "=r"(a[1]), "=r"(a[2]), "=r"(a[3]) : "r"(addr));
}
__device__ __forceinline__ void mma16816(float* d, const uint32_t* a, uint2 b) {
    asm volatile(
        "mma.sync.aligned.m16n8k16.row.col.f32.bf16.bf16.f32 "
        "{%0,%1,%2,%3}, {%4,%5,%6,%7}, {%8,%9}, {%0,%1,%2,%3};"
        : "+f"(d[0]), "+f"(d[1]), "+f"(d[2]), "+f"(d[3])
        : "r"(a[0]), "r"(a[1]), "r"(a[2]), "r"(a[3]), "r"(b.x), "r"(b.y));
}
__device__ __forceinline__ uint32_t smem_u32(const void* p) {
    uint32_t a;
    asm("{ .reg .u64 t; cvta.to.shared.u64 t, %1; cvt.u32.u64 %0, t; }" : "=r"(a) : "l"(p));
    return a;
}

// ---------------------------------------------------------------------------
// Kernel 1: NCHW -> NHWC transpose of x
// ---------------------------------------------------------------------------
__global__ void k_transpose(const float* __restrict__ x) {
    __shared__ float tile[32][33];
    int bh = blockIdx.x;
    int w0 = blockIdx.y * 32;
    int c0 = blockIdx.z * 32;
    int b = bh >> 7;
    const float* src = x + ((size_t)(b * CC) * HH + (bh & 127)) * WW;
#pragma unroll
    for (int i = 0; i < 32; i += 8) {
        int c = c0 + threadIdx.y + i;
        tile[threadIdx.y + i][threadIdx.x] = src[(size_t)c * HH * WW + w0 + threadIdx.x];
    }
    __syncthreads();
    float* dst = g_x + (size_t)bh * WW * CC;
#pragma unroll
    for (int i = 0; i < 32; i += 8) {
        int w = w0 + threadIdx.y + i;
        dst[(size_t)w * CC + c0 + threadIdx.x] = tile[threadIdx.x][threadIdx.y + i];
    }
}

// ---------------------------------------------------------------------------
// Kernel 2: weight -> mma.sync B fragments (bf16 hi/lo), fragment-major order.
// For m16n8k16 row.col: thread 'lane' reg r holds B[k0][n],B[k0+1][n] with
// k0 = (lane&3)*2 + r*8, n = n8*8 + (lane>>2). K dim = tap*64 + c.
// ---------------------------------------------------------------------------
__global__ void k_wfrag(const float* __restrict__ w) {
    int idx = blockIdx.x * 256 + threadIdx.x;  // over 36*8*2*32*2 = 36864
    if (idx >= 36 * 8 * 2 * 64) return;
    int reg = idx & 1;
    int lane = (idx >> 1) & 31;
    int split = (idx >> 6) & 1;
    int n8 = (idx >> 7) & 7;
    int k16 = idx >> 10;
    int n = n8 * 8 + (lane >> 2);
    int k0 = (lane & 3) * 2 + reg * 8;
    int kg = k16 * 16 + k0;      // global K index = tap*64 + c
    int tap = kg >> 6;
    int c = kg & 63;
    float v0 = w[(n * CC + c) * 9 + tap];
    float v1 = w[(n * CC + c + 1) * 9 + tap];
    unsigned short u0, u1;
    if (split == 0) {
        u0 = __bfloat16_as_ushort(__float2bfloat16(v0));
        u1 = __bfloat16_as_ushort(__float2bfloat16(v1));
    } else {
        __nv_bfloat16 h0 = __float2bfloat16(v0), h1 = __float2bfloat16(v1);
        u0 = __bfloat16_as_ushort(__float2bfloat16(v0 - __bfloat162float(h0)));
        u1 = __bfloat16_as_ushort(__float2bfloat16(v1 - __bfloat162float(h1)));
    }
    g_wfrag[idx] = (uint32_t)u0 | ((uint32_t)u1 << 16);
}

// ---------------------------------------------------------------------------
// Kernel 3: offset-predictor conv (unchanged)
// ---------------------------------------------------------------------------
#define WO_FL (9 * 64 * 20)
#define XT_PAD 66
#define XT_FL (18 * 18 * XT_PAD)
#define KOFF_SMEM ((WO_FL + XT_FL) * 4)

__global__ __launch_bounds__(256) void k_off(const float* __restrict__ off_w,
                                             const float* __restrict__ off_b) {
    extern __shared__ float shf[];
    float* wo = shf;
    float* xt = shf + WO_FL;

    int tid = threadIdx.x;
    int b = blockIdx.z;
    int i0 = blockIdx.y * 16, j0 = blockIdx.x * 16;

    for (int idx = tid; idx < WO_FL; idx += 256) {
        int tap = idx / 1280;
        int r = idx - tap * 1280;
        int c = r / 20;
        int oc = r - c * 20;
        wo[idx] = (oc < 18) ? off_w[(oc * CC + c) * 9 + tap] : 0.f;
    }
    const float* xb = g_x + (size_t)b * HH * WW * CC;
    for (int idx = tid; idx < 18 * 18 * 64; idx += 256) {
        int site = idx >> 6, c = idx & 63;
        int ry = site / 18, rx = site - ry * 18;
        int y = i0 + ry - 1, x = j0 + rx - 1;
        float v = 0.f;
        if ((unsigned)y < HH && (unsigned)x < WW) v = xb[((size_t)y * WW + x) * CC + c];
        xt[site * XT_PAD + c] = v;
    }
    __syncthreads();

    int r = tid >> 4, q = tid & 15;

    unsigned long long acc[10];
#pragma unroll
    for (int t = 0; t < 9; t++) acc[t] = pack2(__ldg(&off_b[2 * t]), __ldg(&off_b[2 * t + 1]));
    acc[9] = 0ull;

#pragma unroll
    for (int tap = 0; tap < 9; tap++) {
        const float* xr = &xt[((r + tap / 3) * 18 + (q + tap % 3)) * XT_PAD];
        const float* wt = &wo[tap * 1280];
#pragma unroll 4
        for (int c2 = 0; c2 < 32; c2++) {
            float2 xv = *(const float2*)&xr[c2 * 2];
            unsigned long long xp0 = pack2(xv.x, xv.x);
            unsigned long long xp1 = pack2(xv.y, xv.y);
            const ulonglong2* wv0 = (const ulonglong2*)&wt[(c2 * 2) * 20];
            const ulonglong2* wv1 = (const ulonglong2*)&wt[(c2 * 2 + 1) * 20];
#pragma unroll
            for (int u = 0; u < 5; u++) {
                ulonglong2 w0 = wv0[u];
                ffma2(acc[2 * u], xp0, w0.x);
                ffma2(acc[2 * u + 1], xp0, w0.y);
            }
#pragma unroll
            for (int u = 0; u < 5; u++) {
                ulonglong2 w1 = wv1[u];
                ffma2(acc[2 * u], xp1, w1.x);
                ffma2(acc[2 * u + 1], xp1, w1.y);
            }
        }
    }
    float* outp = g_off + ((size_t)(b * HH + i0 + r) * WW + j0 + q) * 18;
#pragma unroll
    for (int t = 0; t < 9; t++) {
        float2 v = unpack2(acc[t]);
        outp[2 * t] = v.x;
        outp[2 * t + 1] = v.y;
    }
}

// ---------------------------------------------------------------------------
// Kernel 4: main deformable conv, tensor-core contraction.
// grid (W/16, H, B), block 128. One block = 16-pixel output row segment.
// Phase 1: bilinear-gather -> bf16 hi/lo into samp_hi/lo[16][KPAD].
// Phase 2: per warp: N-slice of 16 outputs, K-loop 36x m16n8k16.
//          A (hi,lo) via ldmatrix.x4; B fragments from g_wfrag (dense LDG.64).
//          6 MMAs/step: Ahi*Whi + Ahi*Wlo + Alo*Whi, fp32 accum.
// ---------------------------------------------------------------------------
__global__ __launch_bounds__(128) void k_main(const float* __restrict__ bias,
                                              float* __restrict__ out) {
    __shared__ __align__(16) unsigned short samp_hi[16 * KPAD];  // 18688 B
    __shared__ __align__(16) unsigned short samp_lo[16 * KPAD];  // 18688 B
    __shared__ float offs[16][18];

    int tid = threadIdx.x;
    int b = blockIdx.z, i = blockIdx.y, j0 = blockIdx.x * 16;

    for (int idx = tid; idx < 16 * 18; idx += 128) {
        int p = idx / 18, ch = idx - p * 18;
        offs[p][ch] = g_off[((size_t)(b * HH + i) * WW + j0 + p) * 18 + ch];
    }
    __syncthreads();

    // ---------------- Phase 1: gather (bf16 hi/lo) ----------------
    {
        int g = tid >> 4, lane = tid & 15;
        const float* xb = g_x + (size_t)b * HH * WW * CC;
#pragma unroll 2
        for (int it = 0; it < 18; it++) {
            int pk = it * 8 + g;  // 0..143
            int p = pk / 9, k = pk - p * 9;
            float oy = offs[p][2 * k], ox = offs[p][2 * k + 1];
            float sy = (float)(i + k / 3) + oy;
            float sx = (float)(j0 + p + (k - (k / 3) * 3)) + ox;
            float fy = floorf(sy), fx = floorf(sx);
            float wy1 = sy - fy, wx1 = sx - fx;
            float wy0 = 1.f - wy1, wx0 = 1.f - wx1;
            int iy = (int)fy, ix = (int)fx;
            float tw[4] = {wy0 * wx0, wy0 * wx1, wy1 * wx0, wy1 * wx1};
            int ty[4] = {iy, iy, iy + 1, iy + 1};
            int tx[4] = {ix, ix + 1, ix, ix + 1};
            float acc[4] = {0.f, 0.f, 0.f, 0.f};
#pragma unroll
            for (int tapi = 0; tapi < 4; tapi++) {
                int yy = ty[tapi], xx = tx[tapi];
                if ((unsigned)yy < HH && (unsigned)xx < WW) {
                    float4 xv =
                        *(const float4*)(xb + ((size_t)yy * WW + xx) * CC + lane * 4);
                    float w = tw[tapi];
                    acc[0] += w * xv.x;
                    acc[1] += w * xv.y;
                    acc[2] += w * xv.z;
                    acc[3] += w * xv.w;
                }
            }
            // split to bf16 hi/lo and store 4 elems (8B) to each array
            unsigned short h[4], l[4];
#pragma unroll
            for (int u = 0; u < 4; u++) {
                __nv_bfloat16 hb = __float2bfloat16(acc[u]);
                h[u] = __bfloat16_as_ushort(hb);
                l[u] = __bfloat16_as_ushort(
                    __float2bfloat16(acc[u] - __bfloat162float(hb)));
            }
            int o = p * KPAD + k * 64 + lane * 4;
            *(uint2*)&samp_hi[o] =
                make_uint2((uint32_t)h[0] | ((uint32_t)h[1] << 16),
                           (uint32_t)h[2] | ((uint32_t)h[3] << 16));
            *(uint2*)&samp_lo[o] =
                make_uint2((uint32_t)l[0] | ((uint32_t)l[1] << 16),
                           (uint32_t)l[2] | ((uint32_t)l[3] << 16));
        }
    }
    __syncthreads();

    // ---------------- Phase 2: tensor-core contraction ----------------
    int wid = tid >> 5, lane = tid & 31;
    // ldmatrix lane addressing: row = lane&15 (pixel), koff = (lane>>4)*8
    int arow = lane & 15;
    int akoff = (lane >> 4) * 8;
    uint32_t aHbase = smem_u32(samp_hi) + (uint32_t)(arow * KPAD + akoff) * 2;
    uint32_t aLbase = smem_u32(samp_lo) + (uint32_t)(arow * KPAD + akoff) * 2;

    float d0[4] = {0.f, 0.f, 0.f, 0.f};  // n8 = wid*2
    float d1[4] = {0.f, 0.f, 0.f, 0.f};  // n8 = wid*2+1
    const uint2* wf = (const uint2*)g_wfrag;  // [k16][n8][split][lane(.2regs)]

#pragma unroll 4
    for (int k16 = 0; k16 < 36; k16++) {
        uint32_t aH[4], aL[4];
        ldmat4(aH, aHbase + k16 * 32);  // 16 ushort = 32B per kstep
        ldmat4(aL, aLbase + k16 * 32);
        int base = (k16 * 8 + wid * 2) * 2;  // uint2 index: ((k16*8+n8)*2+split)*32+lane
        uint2 bH0 = wf[(base + 0) * 32 + lane];
        uint2 bL0 = wf[(base + 1) * 32 + lane];
        uint2 bH1 = wf[(base + 2) * 32 + lane];
        uint2 bL1 = wf[(base + 3) * 32 + lane];
        mma16816(d0, aH, bH0);
        mma16816(d0, aH, bL0);
        mma16816(d0, aL, bH0);
        mma16816(d1, aH, bH1);
        mma16816(d1, aH, bL1);
        mma16816(d1, aL, bH1);
    }

    __syncthreads();  // samp fully consumed; reuse as f32 reduction buffer
    float* red = (float*)samp_hi;  // 16 px x 64 o = 4096 floats (fits)
    {
        int row = lane >> 2;
        int o0 = wid * 16 + (lane & 3) * 2;
        red[row * 64 + o0] = d0[0];
        red[row * 64 + o0 + 1] = d0[1];
        red[(row + 8) * 64 + o0] = d0[2];
        red[(row + 8) * 64 + o0 + 1] = d0[3];
        red[row * 64 + o0 + 8] = d1[0];
        red[row * 64 + o0 + 9] = d1[1];
        red[(row + 8) * 64 + o0 + 8] = d1[2];
        red[(row + 8) * 64 + o0 + 9] = d1[3];
    }
    __syncthreads();

    // coalesced NCHW store + bias
    for (int idx = tid; idx < 1024; idx += 128) {
        int oo = idx >> 4, p = idx & 15;
        float v = red[p * 64 + oo] + __ldg(&bias[oo]);
        out[((size_t)(b * OO + oo) * HH + i) * WW + j0 + p] = v;
    }
}

// ---------------------------------------------------------------------------
extern "C" void kernel_launch(void* const* d_in, const int* in_sizes, int n_in,
                              void* d_out, int out_size) {
    const float* x = (const float*)d_in[0];
    const float* weight = (const float*)d_in[1];
    const float* bias = (const float*)d_in[2];
    const float* off_w = (const float*)d_in[3];
    const float* off_b = (const float*)d_in[4];
    float* out = (float*)d_out;

    cudaFuncSetAttribute(k_off, cudaFuncAttributeMaxDynamicSharedMemorySize, KOFF_SMEM);

    k_transpose<<<dim3(BB * HH, WW / 32, CC / 32), dim3(32, 8)>>>(x);
    k_wfrag<<<(36 * 8 * 2 * 64 + 255) / 256, 256>>>(weight);
    k_off<<<dim3(WW / 16, HH / 16, BB), 256, KOFF_SMEM>>>(off_w, off_b);
    k_main<<<dim3(WW / 16, HH, BB), 128>>>(bias, out);
}